// round 5
// baseline (speedup 1.0000x reference)
#include <cuda_runtime.h>
#include <cstdint>
#include <cstddef>
#include <math.h>

#define BB 16
#define LL 1024
#define DD 128
#define HH 256

typedef unsigned long long u64;
struct __align__(16) ull2 { u64 x, y; };

// Scratch: filtered spectrum, interleaved complex (re,im) per element.
__device__ float g_F[(size_t)BB * LL * DD * 2];
__device__ float g_scale[BB * DD];
__device__ float g_bias[BB * DD];

__device__ __forceinline__ float gelu_exact(float v) {
    return 0.5f * v * (1.0f + erff(v * 0.70710678118654752f));
}

// ---- f32x2 packed helpers (Blackwell FFMA2 path; ptxas won't auto-fuse) ----
__device__ __forceinline__ u64 dup2(float a) {
    u64 r; asm("mov.b64 %0, {%1, %1};" : "=l"(r) : "f"(a)); return r;
}
__device__ __forceinline__ void unpack2(u64 v, float& a, float& b) {
    asm("mov.b64 {%0, %1}, %2;" : "=f"(a), "=f"(b) : "l"(v));
}
__device__ __forceinline__ void ffma2(u64& d, u64 a, u64 b) {
    asm("fma.rn.f32x2 %0, %1, %2, %0;" : "+l"(d) : "l"(a), "l"(b));
}

// One block per batch: c1/c2 reductions + the four 128->256->128 MLPs.
// Produces scale[b][d] = 1 + 0.5*(W1+W2), bias[b][d] = 0.5*(b1+b2).
__global__ __launch_bounds__(256) void setup_kernel(
    const float* __restrict__ y, const float* __restrict__ z,
    const int* __restrict__ len_y, const int* __restrict__ len_z,
    const float* __restrict__ W1w1, const float* __restrict__ W1b1,
    const float* __restrict__ W1w2, const float* __restrict__ W1b2,
    const float* __restrict__ B1w1, const float* __restrict__ B1b1,
    const float* __restrict__ B1w2, const float* __restrict__ B1b2,
    const float* __restrict__ W2w1, const float* __restrict__ W2b1,
    const float* __restrict__ W2w2, const float* __restrict__ W2b2,
    const float* __restrict__ B2w1, const float* __restrict__ B2b1,
    const float* __restrict__ B2w2, const float* __restrict__ B2b2)
{
    __shared__ float c1[DD], c2[DD];
    __shared__ float hW1[HH], hB1[HH], hW2[HH], hB2[HH];
    const int b = blockIdx.x;
    const int tid = threadIdx.x;

    // c1 = sum(y, axis=1)/len_y ; c2 = sum(z, axis=1)/len_z (sum over ALL L rows)
    {
        const int d = tid & 127;
        const float* src = (tid < 128) ? y : z;
        const float* p = src + (size_t)b * LL * DD + d;
        float acc = 0.f;
        #pragma unroll 8
        for (int t = 0; t < LL; ++t) acc += p[(size_t)t * DD];
        const float len = (float)((tid < 128) ? len_y[b] : len_z[b]);
        if (tid < 128) c1[d] = acc / len; else c2[d] = acc / len;
    }
    __syncthreads();

    // Layer 1 (D->H) for all four MLPs; j = tid in [0,256)
    {
        const int j = tid;
        float a1 = W1b1[j], a2 = B1b1[j], a3 = W2b1[j], a4 = B2b1[j];
        #pragma unroll 4
        for (int d = 0; d < DD; ++d) {
            const float v1 = c1[d], v2 = c2[d];
            a1 += v1 * W1w1[d * HH + j];
            a2 += v1 * B1w1[d * HH + j];
            a3 += v2 * W2w1[d * HH + j];
            a4 += v2 * B2w1[d * HH + j];
        }
        hW1[j] = gelu_exact(a1);
        hB1[j] = gelu_exact(a2);
        hW2[j] = gelu_exact(a3);
        hB2[j] = gelu_exact(a4);
    }
    __syncthreads();

    // Layer 2 (H->D): threads 0..127 -> scale, 128..255 -> bias
    if (tid < 128) {
        const int d = tid;
        float a1 = W1b2[d], a3 = W2b2[d];
        #pragma unroll 4
        for (int j = 0; j < HH; ++j) {
            a1 += hW1[j] * W1w2[j * DD + d];
            a3 += hW2[j] * W2w2[j * DD + d];
        }
        g_scale[b * DD + d] = 1.0f + 0.5f * (a1 + a3);
    } else {
        const int d = tid - 128;
        float a2 = B1b2[d], a4 = B2b2[d];
        #pragma unroll 4
        for (int j = 0; j < HH; ++j) {
            a2 += hB1[j] * B1w2[j * DD + d];
            a4 += hB2[j] * B2w2[j * DD + d];
        }
        g_bias[b * DD + d] = 0.5f * (a2 + a4);
    }
}

// Forward ragged DFT + filter epilogue, packed (re,im) accumulators.
// tw[m] = (cos(2*pi*m/l), -sin(2*pi*m/l));  F = sum_t tw[(k*t)%l] * x  (elementwise packed)
// filtered = F*scale + (bias, 0); complex-relu is identity. Rows k>=l never consumed.
__global__ __launch_bounds__(256) void fwd_kernel(const float* __restrict__ x,
                                                  const int* __restrict__ len_x)
{
    const int b = blockIdx.y;
    const int l = len_x[b];
    const int k0 = blockIdx.x * 32;
    if (k0 >= l) return;

    __shared__ float2 tw[LL];       // (cos, -sin)
    __shared__ float xs[32][DD];

    const int tid = threadIdx.x;
    const float invl = 1.0f / (float)l;
    for (int m = tid; m < l; m += 256) {
        float s, c;
        sincosf(6.283185307179586f * (float)m * invl, &s, &c);
        tw[m] = make_float2(c, -s);
    }

    const int dgrp = tid & 31;      // 4 contiguous d's per thread
    const int kq = tid >> 5;        // warp-uniform -> twiddle lookups broadcast
    int kk[4], mm[4], ks[4];
    #pragma unroll
    for (int i = 0; i < 4; ++i) { kk[i] = k0 + kq * 4 + i; ks[i] = kk[i] % l; mm[i] = 0; }

    u64 acc[4][4] = {};             // packed (re, im) per (k_i, d_j)

    for (int t0 = 0; t0 < l; t0 += 32) {
        __syncthreads();   // first iter: covers table build; later: protects xs reuse
        for (int idx = tid; idx < 32 * DD; idx += 256) {
            const int t = t0 + (idx >> 7);
            xs[idx >> 7][idx & 127] =
                (t < l) ? x[(size_t)b * LL * DD + (size_t)t * DD + (idx & 127)] : 0.f;
        }
        __syncthreads();
        #pragma unroll 8
        for (int tt = 0; tt < 32; ++tt) {
            const float4 xv = *reinterpret_cast<const float4*>(&xs[tt][dgrp * 4]);
            const u64 xx0 = dup2(xv.x), xx1 = dup2(xv.y);
            const u64 xx2 = dup2(xv.z), xx3 = dup2(xv.w);
            #pragma unroll
            for (int i = 0; i < 4; ++i) {
                const u64 w = *reinterpret_cast<const u64*>(&tw[mm[i]]);
                ffma2(acc[i][0], w, xx0);
                ffma2(acc[i][1], w, xx1);
                ffma2(acc[i][2], w, xx2);
                ffma2(acc[i][3], w, xx3);
                mm[i] += ks[i]; if (mm[i] >= l) mm[i] -= l;
            }
        }
    }

    // Epilogue: (re,im) -> (re*sc + bi, im*sc), stored interleaved.
    const float4 sc = *reinterpret_cast<const float4*>(&g_scale[b * DD + dgrp * 4]);
    const float4 bi = *reinterpret_cast<const float4*>(&g_bias[b * DD + dgrp * 4]);
    const float scv[4] = {sc.x, sc.y, sc.z, sc.w};
    const float biv[4] = {bi.x, bi.y, bi.z, bi.w};
    #pragma unroll
    for (int i = 0; i < 4; ++i) {
        const int k = kk[i];
        if (k < l) {
            float o[8];
            #pragma unroll
            for (int j = 0; j < 4; ++j) {
                float re, im; unpack2(acc[i][j], re, im);
                o[2 * j]     = re * scv[j] + biv[j];
                o[2 * j + 1] = im * scv[j];
            }
            const size_t off = (((size_t)b * LL + k) * DD + dgrp * 4) * 2;
            *reinterpret_cast<float4*>(&g_F[off])     = make_float4(o[0], o[1], o[2], o[3]);
            *reinterpret_cast<float4*>(&g_F[off + 4]) = make_float4(o[4], o[5], o[6], o[7]);
        }
    }
}

// Inverse ragged DFT: out[b,k,d] = (1/l) * sum_{t<l} [cos*Fre - sin*Fim], k<l; else 0.
// Packed: acc += (cos,-sin) .* (Fre,Fim); result = (lo+hi)/l.
__global__ __launch_bounds__(256) void inv_kernel(float* __restrict__ out,
                                                  const int* __restrict__ len_x)
{
    const int b = blockIdx.y;
    const int l = len_x[b];
    const int k0 = blockIdx.x * 32;
    const int tid = threadIdx.x;

    if (k0 >= l) {  // whole tile past l: zero-fill output (buffer is poisoned)
        for (int idx = tid; idx < 32 * DD; idx += 256) {
            const int k = k0 + (idx >> 7);
            out[((size_t)b * LL + k) * DD + (idx & 127)] = 0.f;
        }
        return;
    }

    __shared__ float2 tw[LL];           // (cos, -sin)
    __shared__ float fs[32][DD * 2];    // interleaved (re,im) rows

    const float invl = 1.0f / (float)l;
    for (int m = tid; m < l; m += 256) {
        float s, c;
        sincosf(6.283185307179586f * (float)m * invl, &s, &c);
        tw[m] = make_float2(c, -s);
    }

    const int dgrp = tid & 31;
    const int kq = tid >> 5;
    int kk[4], mm[4], ks[4];
    #pragma unroll
    for (int i = 0; i < 4; ++i) { kk[i] = k0 + kq * 4 + i; ks[i] = kk[i] % l; mm[i] = 0; }

    u64 acc[4][4] = {};   // packed (cos-part, sin-part) partial sums

    for (int t0 = 0; t0 < l; t0 += 32) {
        __syncthreads();
        for (int idx = tid; idx < 32 * (DD * 2 / 4); idx += 256) {   // float4 granularity
            const int r = idx / (DD * 2 / 4);       // row 0..31
            const int c4 = idx % (DD * 2 / 4);      // float4 col
            const int t = t0 + r;
            float4 v = make_float4(0.f, 0.f, 0.f, 0.f);
            if (t < l)
                v = *reinterpret_cast<const float4*>(
                        &g_F[(((size_t)b * LL + t) * DD) * 2 + c4 * 4]);
            *reinterpret_cast<float4*>(&fs[r][c4 * 4]) = v;
        }
        __syncthreads();
        #pragma unroll 8
        for (int tt = 0; tt < 32; ++tt) {
            const ull2 q0 = *reinterpret_cast<const ull2*>(&fs[tt][dgrp * 8]);
            const ull2 q1 = *reinterpret_cast<const ull2*>(&fs[tt][dgrp * 8 + 4]);
            #pragma unroll
            for (int i = 0; i < 4; ++i) {
                const u64 w = *reinterpret_cast<const u64*>(&tw[mm[i]]);
                ffma2(acc[i][0], w, q0.x);
                ffma2(acc[i][1], w, q0.y);
                ffma2(acc[i][2], w, q1.x);
                ffma2(acc[i][3], w, q1.y);
                mm[i] += ks[i]; if (mm[i] >= l) mm[i] -= l;
            }
        }
    }

    #pragma unroll
    for (int i = 0; i < 4; ++i) {
        const int k = kk[i];
        float4 o = make_float4(0.f, 0.f, 0.f, 0.f);
        if (k < l) {
            float lo, hi;
            unpack2(acc[i][0], lo, hi); o.x = (lo + hi) * invl;
            unpack2(acc[i][1], lo, hi); o.y = (lo + hi) * invl;
            unpack2(acc[i][2], lo, hi); o.z = (lo + hi) * invl;
            unpack2(acc[i][3], lo, hi); o.w = (lo + hi) * invl;
        }
        *reinterpret_cast<float4*>(&out[((size_t)b * LL + k) * DD + dgrp * 4]) = o;
    }
}

extern "C" void kernel_launch(void* const* d_in, const int* in_sizes, int n_in,
                              void* d_out, int out_size)
{
    const float* x     = (const float*)d_in[0];
    const float* y     = (const float*)d_in[1];
    const float* z     = (const float*)d_in[2];
    const int*   len_x = (const int*)d_in[3];
    const int*   len_y = (const int*)d_in[4];
    const int*   len_z = (const int*)d_in[5];

    setup_kernel<<<BB, 256>>>(y, z, len_y, len_z,
        (const float*)d_in[6],  (const float*)d_in[7],  (const float*)d_in[8],  (const float*)d_in[9],
        (const float*)d_in[10], (const float*)d_in[11], (const float*)d_in[12], (const float*)d_in[13],
        (const float*)d_in[14], (const float*)d_in[15], (const float*)d_in[16], (const float*)d_in[17],
        (const float*)d_in[18], (const float*)d_in[19], (const float*)d_in[20], (const float*)d_in[21]);

    fwd_kernel<<<dim3(LL / 32, BB), 256>>>(x, len_x);
    inv_kernel<<<dim3(LL / 32, BB), 256>>>((float*)d_out, len_x);
}

// round 9
// speedup vs baseline: 1.0448x; 1.0448x over previous
#include <cuda_runtime.h>
#include <cstdint>
#include <cstddef>
#include <math.h>

#define BB 16
#define LL 1024
#define DD 128
#define HH 256
#define NSEG 16
#define TWO_PI 6.283185307179586f

typedef unsigned long long u64;
struct __align__(16) ull2 { u64 x, y; };

// Scratch: filtered spectrum (planar re/im), partial sums, filter params.
__device__ float g_Fre[(size_t)BB * LL * DD];
__device__ float g_Fim[(size_t)BB * LL * DD];
__device__ float g_part[2 * BB * NSEG * DD];
__device__ float g_scale[BB * DD];
__device__ float g_bias[BB * DD];

__device__ __forceinline__ float gelu_exact(float v) {
    return 0.5f * v * (1.0f + erff(v * 0.70710678118654752f));
}

// ---- f32x2 packed helpers (Blackwell FFMA2 path; ptxas won't auto-fuse) ----
__device__ __forceinline__ u64 pack2(float a, float b) {
    u64 r; asm("mov.b64 %0, {%1, %2};" : "=l"(r) : "f"(a), "f"(b)); return r;
}
__device__ __forceinline__ void unpack2(u64 v, float& a, float& b) {
    asm("mov.b64 {%0, %1}, %2;" : "=f"(a), "=f"(b) : "l"(v));
}
__device__ __forceinline__ void ffma2(u64& d, u64 a, u64 b) {
    asm("fma.rn.f32x2 %0, %1, %2, %0;" : "+l"(d) : "l"(a), "l"(b));
}

// ---------------- setup stage 1: partial row-sums of y and z ----------------
// grid (NSEG, 2*BB), block 128. Each block sums 64 rows of one (src,b) slice.
__global__ __launch_bounds__(128) void part_kernel(const float* __restrict__ y,
                                                   const float* __restrict__ z)
{
    const int seg = blockIdx.x;
    const int b   = blockIdx.y >> 1;
    const int src = blockIdx.y & 1;
    const int d   = threadIdx.x;
    const float* p = (src ? z : y) + (size_t)b * LL * DD + (size_t)seg * 64 * DD + d;
    float acc = 0.f;
    #pragma unroll 16
    for (int r = 0; r < 64; ++r) acc += p[(size_t)r * DD];
    g_part[((size_t)(src * BB + b) * NSEG + seg) * DD + d] = acc;
}

// ---------------- setup stage 2: the four 128->256->128 MLPs ----------------
// grid BB, block 256. scale = 1 + 0.5*(W1+W2), bias = 0.5*(b1+b2).
__global__ __launch_bounds__(256) void mlp_kernel(
    const int* __restrict__ len_y, const int* __restrict__ len_z,
    const float* __restrict__ W1w1, const float* __restrict__ W1b1,
    const float* __restrict__ W1w2, const float* __restrict__ W1b2,
    const float* __restrict__ B1w1, const float* __restrict__ B1b1,
    const float* __restrict__ B1w2, const float* __restrict__ B1b2,
    const float* __restrict__ W2w1, const float* __restrict__ W2b1,
    const float* __restrict__ W2w2, const float* __restrict__ W2b2,
    const float* __restrict__ B2w1, const float* __restrict__ B2b1,
    const float* __restrict__ B2w2, const float* __restrict__ B2b2)
{
    __shared__ float c1[DD], c2[DD];
    __shared__ float hW1[HH], hB1[HH], hW2[HH], hB2[HH];
    const int b = blockIdx.x;
    const int tid = threadIdx.x;

    if (tid < 128) {
        const int d = tid;
        float s = 0.f;
        #pragma unroll
        for (int seg = 0; seg < NSEG; ++seg)
            s += g_part[((size_t)b * NSEG + seg) * DD + d];
        c1[d] = s / (float)len_y[b];
    } else {
        const int d = tid - 128;
        float s = 0.f;
        #pragma unroll
        for (int seg = 0; seg < NSEG; ++seg)
            s += g_part[((size_t)(BB + b) * NSEG + seg) * DD + d];
        c2[d] = s / (float)len_z[b];
    }
    __syncthreads();

    {   // Layer 1 (D->H) for all four MLPs; j = tid in [0,256)
        const int j = tid;
        float a1 = W1b1[j], a2 = B1b1[j], a3 = W2b1[j], a4 = B2b1[j];
        #pragma unroll 8
        for (int d = 0; d < DD; ++d) {
            const float v1 = c1[d], v2 = c2[d];
            a1 += v1 * W1w1[d * HH + j];
            a2 += v1 * B1w1[d * HH + j];
            a3 += v2 * W2w1[d * HH + j];
            a4 += v2 * B2w1[d * HH + j];
        }
        hW1[j] = gelu_exact(a1);
        hB1[j] = gelu_exact(a2);
        hW2[j] = gelu_exact(a3);
        hB2[j] = gelu_exact(a4);
    }
    __syncthreads();

    if (tid < 128) {
        const int d = tid;
        float a1 = W1b2[d], a3 = W2b2[d];
        #pragma unroll 8
        for (int j = 0; j < HH; ++j) {
            a1 += hW1[j] * W1w2[j * DD + d];
            a3 += hW2[j] * W2w2[j * DD + d];
        }
        g_scale[b * DD + d] = 1.0f + 0.5f * (a1 + a3);
    } else {
        const int d = tid - 128;
        float a2 = B1b2[d], a4 = B2b2[d];
        #pragma unroll 8
        for (int j = 0; j < HH; ++j) {
            a2 += hB1[j] * B1w2[j * DD + d];
            a4 += hB2[j] * B2w2[j * DD + d];
        }
        g_bias[b * DD + d] = 0.5f * (a2 + a4);
    }
}

// ---------------- Forward ragged DFT + filter epilogue ----------------
// tw4[m] = {(c,c),(-s,-s)} of 2*pi*m/l, one LDS.128 per k per t-step.
// Block: 8 warps x 4 k = 32 k; lane g owns d = 4g..4g+3 (2 packed d-pairs).
__global__ __launch_bounds__(256) void fwd_kernel(const float* __restrict__ x,
                                                  const int* __restrict__ len_x)
{
    const int b = blockIdx.y;
    const int l = len_x[b];
    const int k0 = blockIdx.x * 32;
    if (k0 >= l) return;

    __shared__ ull2 tw4[LL];
    __shared__ __align__(16) float xs[32][DD];

    const int tid = threadIdx.x;
    const float invl = 1.0f / (float)l;
    for (int m = tid; m < l; m += 256) {
        float s, c;
        sincosf(TWO_PI * (float)m * invl, &s, &c);
        ull2 w; w.x = pack2(c, c); w.y = pack2(-s, -s);
        tw4[m] = w;
    }

    const int g = tid & 31;
    const int kq = tid >> 5;
    int kk[4], mm[4], ks[4];
    #pragma unroll
    for (int i = 0; i < 4; ++i) { kk[i] = k0 + kq * 4 + i; ks[i] = kk[i] % l; mm[i] = 0; }

    u64 ar[4][2] = {}, ai[4][2] = {};   // packed (d,d+1) re / im accumulators

    const float* xb_ = x + (size_t)b * LL * DD;
    float4 pf[4];

#define FWD_LOAD(T0) do {                                                   \
        _Pragma("unroll")                                                   \
        for (int j = 0; j < 4; ++j) {                                       \
            const int f4 = tid + 256 * j;                                   \
            const int r = f4 >> 5, cc = (f4 & 31) * 4;                      \
            const int t = (T0) + r;                                         \
            pf[j] = (t < l) ? *reinterpret_cast<const float4*>(             \
                                  &xb_[(size_t)t * DD + cc])                \
                            : make_float4(0.f, 0.f, 0.f, 0.f);              \
        }                                                                   \
    } while (0)

    FWD_LOAD(0);
    for (int t0 = 0; t0 < l; t0 += 32) {
        #pragma unroll
        for (int j = 0; j < 4; ++j) {
            const int f4 = tid + 256 * j;
            *reinterpret_cast<float4*>(&xs[f4 >> 5][(f4 & 31) * 4]) = pf[j];
        }
        __syncthreads();                 // first iter also covers table build
        if (t0 + 32 < l) FWD_LOAD(t0 + 32);   // LDGs in flight during compute
        #pragma unroll 4
        for (int tt = 0; tt < 32; ++tt) {
            const ull2 xa = *reinterpret_cast<const ull2*>(&xs[tt][g * 4]);
            #pragma unroll
            for (int i = 0; i < 4; ++i) {
                const ull2 w = tw4[mm[i]];
                ffma2(ar[i][0], w.x, xa.x); ffma2(ar[i][1], w.x, xa.y);
                ffma2(ai[i][0], w.y, xa.x); ffma2(ai[i][1], w.y, xa.y);
                mm[i] += ks[i]; if (mm[i] >= l) mm[i] -= l;
            }
        }
        __syncthreads();
    }
#undef FWD_LOAD

    // Epilogue: filtered = F*scale + (bias,0); complex-relu is identity.
    const float4 sc = *reinterpret_cast<const float4*>(&g_scale[b * DD + g * 4]);
    const float4 bi = *reinterpret_cast<const float4*>(&g_bias[b * DD + g * 4]);
    #pragma unroll
    for (int i = 0; i < 4; ++i) {
        const int k = kk[i];
        if (k < l) {
            float r0, r1, r2, r3, q0, q1, q2, q3;
            unpack2(ar[i][0], r0, r1); unpack2(ar[i][1], r2, r3);
            unpack2(ai[i][0], q0, q1); unpack2(ai[i][1], q2, q3);
            const size_t base = ((size_t)b * LL + k) * DD + g * 4;
            *reinterpret_cast<float4*>(&g_Fre[base]) =
                make_float4(r0*sc.x+bi.x, r1*sc.y+bi.y, r2*sc.z+bi.z, r3*sc.w+bi.w);
            *reinterpret_cast<float4*>(&g_Fim[base]) =
                make_float4(q0*sc.x, q1*sc.y, q2*sc.z, q3*sc.w);
        }
    }
}

// ---------------- Inverse ragged DFT ----------------
// out[b,k,d] = (1/l) * sum_{t<l} [cos*Fre + (-sin)*Fim], k<l; else 0.
__global__ __launch_bounds__(256) void inv_kernel(float* __restrict__ out,
                                                  const int* __restrict__ len_x)
{
    const int b = blockIdx.y;
    const int l = len_x[b];
    const int k0 = blockIdx.x * 32;
    const int tid = threadIdx.x;

    if (k0 >= l) {  // whole tile past l: zero-fill output (buffer is poisoned)
        for (int idx = tid; idx < 32 * DD; idx += 256) {
            const int k = k0 + (idx >> 7);
            out[((size_t)b * LL + k) * DD + (idx & 127)] = 0.f;
        }
        return;
    }

    __shared__ ull2 tw4[LL];
    __shared__ __align__(16) float fre[32][DD];
    __shared__ __align__(16) float fim[32][DD];

    const float invl = 1.0f / (float)l;
    for (int m = tid; m < l; m += 256) {
        float s, c;
        sincosf(TWO_PI * (float)m * invl, &s, &c);
        ull2 w; w.x = pack2(c, c); w.y = pack2(-s, -s);
        tw4[m] = w;
    }

    const int g = tid & 31;
    const int kq = tid >> 5;
    int kk[4], mm[4], ks[4];
    #pragma unroll
    for (int i = 0; i < 4; ++i) { kk[i] = k0 + kq * 4 + i; ks[i] = kk[i] % l; mm[i] = 0; }

    u64 acc[4][2] = {};   // packed (d,d+1) output accumulators

    const float* fre_g = g_Fre + (size_t)b * LL * DD;
    const float* fim_g = g_Fim + (size_t)b * LL * DD;
    float4 pr[4], pi[4];

#define INV_LOAD(T0) do {                                                   \
        _Pragma("unroll")                                                   \
        for (int j = 0; j < 4; ++j) {                                       \
            const int f4 = tid + 256 * j;                                   \
            const int r = f4 >> 5, cc = (f4 & 31) * 4;                      \
            const int t = (T0) + r;                                         \
            if (t < l) {                                                    \
                const size_t o = (size_t)t * DD + cc;                       \
                pr[j] = *reinterpret_cast<const float4*>(&fre_g[o]);        \
                pi[j] = *reinterpret_cast<const float4*>(&fim_g[o]);        \
            } else {                                                        \
                pr[j] = make_float4(0.f, 0.f, 0.f, 0.f);                    \
                pi[j] = make_float4(0.f, 0.f, 0.f, 0.f);                    \
            }                                                               \
        }                                                                   \
    } while (0)

    INV_LOAD(0);
    for (int t0 = 0; t0 < l; t0 += 32) {
        #pragma unroll
        for (int j = 0; j < 4; ++j) {
            const int f4 = tid + 256 * j;
            *reinterpret_cast<float4*>(&fre[f4 >> 5][(f4 & 31) * 4]) = pr[j];
            *reinterpret_cast<float4*>(&fim[f4 >> 5][(f4 & 31) * 4]) = pi[j];
        }
        __syncthreads();
        if (t0 + 32 < l) INV_LOAD(t0 + 32);
        #pragma unroll 4
        for (int tt = 0; tt < 32; ++tt) {
            const ull2 fa = *reinterpret_cast<const ull2*>(&fre[tt][g * 4]);
            const ull2 ga = *reinterpret_cast<const ull2*>(&fim[tt][g * 4]);
            #pragma unroll
            for (int i = 0; i < 4; ++i) {
                const ull2 w = tw4[mm[i]];
                ffma2(acc[i][0], w.x, fa.x); ffma2(acc[i][0], w.y, ga.x);
                ffma2(acc[i][1], w.x, fa.y); ffma2(acc[i][1], w.y, ga.y);
                mm[i] += ks[i]; if (mm[i] >= l) mm[i] -= l;
            }
        }
        __syncthreads();
    }
#undef INV_LOAD

    #pragma unroll
    for (int i = 0; i < 4; ++i) {
        const int k = kk[i];
        float o0 = 0.f, o1 = 0.f, o2 = 0.f, o3 = 0.f;
        if (k < l) {
            unpack2(acc[i][0], o0, o1); unpack2(acc[i][1], o2, o3);
            o0 *= invl; o1 *= invl; o2 *= invl; o3 *= invl;
        }
        *reinterpret_cast<float4*>(&out[((size_t)b * LL + k) * DD + g * 4]) =
            make_float4(o0, o1, o2, o3);
    }
}

extern "C" void kernel_launch(void* const* d_in, const int* in_sizes, int n_in,
                              void* d_out, int out_size)
{
    const float* x     = (const float*)d_in[0];
    const float* y     = (const float*)d_in[1];
    const float* z     = (const float*)d_in[2];
    const int*   len_x = (const int*)d_in[3];
    const int*   len_y = (const int*)d_in[4];
    const int*   len_z = (const int*)d_in[5];

    part_kernel<<<dim3(NSEG, 2 * BB), 128>>>(y, z);
    mlp_kernel<<<BB, 256>>>(len_y, len_z,
        (const float*)d_in[6],  (const float*)d_in[7],  (const float*)d_in[8],  (const float*)d_in[9],
        (const float*)d_in[10], (const float*)d_in[11], (const float*)d_in[12], (const float*)d_in[13],
        (const float*)d_in[14], (const float*)d_in[15], (const float*)d_in[16], (const float*)d_in[17],
        (const float*)d_in[18], (const float*)d_in[19], (const float*)d_in[20], (const float*)d_in[21]);

    fwd_kernel<<<dim3(LL / 32, BB), 256>>>(x, len_x);
    inv_kernel<<<dim3(LL / 32, BB), 256>>>((float*)d_out, len_x);
}

// round 13
// speedup vs baseline: 1.7360x; 1.6616x over previous
#include <cuda_runtime.h>
#include <cstdint>
#include <cstddef>
#include <math.h>

#define BB 16
#define LL 1024
#define DD 128
#define HH 256
#define NSEG 16
#define TWO_PI 6.283185307179586f

typedef unsigned long long u64;
struct __align__(16) ull2 { u64 x, y; };

// Scratch: filtered half-spectrum (planar re/im, conj-symmetric weights folded),
// partial sums, filter params.
__device__ float g_Fre[(size_t)BB * LL * DD];
__device__ float g_Fim[(size_t)BB * LL * DD];
__device__ float g_part[2 * BB * NSEG * DD];
__device__ float g_scale[BB * DD];
__device__ float g_bias[BB * DD];

__device__ __forceinline__ float gelu_exact(float v) {
    return 0.5f * v * (1.0f + erff(v * 0.70710678118654752f));
}

// ---- f32x2 packed helpers (Blackwell FFMA2 path; ptxas won't auto-fuse) ----
__device__ __forceinline__ u64 pack2(float a, float b) {
    u64 r; asm("mov.b64 %0, {%1, %2};" : "=l"(r) : "f"(a), "f"(b)); return r;
}
__device__ __forceinline__ void unpack2(u64 v, float& a, float& b) {
    asm("mov.b64 {%0, %1}, %2;" : "=f"(a), "=f"(b) : "l"(v));
}
__device__ __forceinline__ void ffma2(u64& d, u64 a, u64 b) {
    asm("fma.rn.f32x2 %0, %1, %2, %0;" : "+l"(d) : "l"(a), "l"(b));
}

// ---------------- setup stage 1: partial row-sums of y and z ----------------
__global__ __launch_bounds__(128) void part_kernel(const float* __restrict__ y,
                                                   const float* __restrict__ z)
{
    const int seg = blockIdx.x;
    const int b   = blockIdx.y >> 1;
    const int src = blockIdx.y & 1;
    const int d   = threadIdx.x;
    const float* p = (src ? z : y) + (size_t)b * LL * DD + (size_t)seg * 64 * DD + d;
    float acc = 0.f;
    #pragma unroll 16
    for (int r = 0; r < 64; ++r) acc += p[(size_t)r * DD];
    g_part[((size_t)(src * BB + b) * NSEG + seg) * DD + d] = acc;
}

// ---------------- setup stage 2: the four 128->256->128 MLPs ----------------
__global__ __launch_bounds__(256) void mlp_kernel(
    const int* __restrict__ len_y, const int* __restrict__ len_z,
    const float* __restrict__ W1w1, const float* __restrict__ W1b1,
    const float* __restrict__ W1w2, const float* __restrict__ W1b2,
    const float* __restrict__ B1w1, const float* __restrict__ B1b1,
    const float* __restrict__ B1w2, const float* __restrict__ B1b2,
    const float* __restrict__ W2w1, const float* __restrict__ W2b1,
    const float* __restrict__ W2w2, const float* __restrict__ W2b2,
    const float* __restrict__ B2w1, const float* __restrict__ B2b1,
    const float* __restrict__ B2w2, const float* __restrict__ B2b2)
{
    __shared__ float c1[DD], c2[DD];
    __shared__ float hW1[HH], hB1[HH], hW2[HH], hB2[HH];
    const int b = blockIdx.x;
    const int tid = threadIdx.x;

    if (tid < 128) {
        const int d = tid;
        float s = 0.f;
        #pragma unroll
        for (int seg = 0; seg < NSEG; ++seg)
            s += g_part[((size_t)b * NSEG + seg) * DD + d];
        c1[d] = s / (float)len_y[b];
    } else {
        const int d = tid - 128;
        float s = 0.f;
        #pragma unroll
        for (int seg = 0; seg < NSEG; ++seg)
            s += g_part[((size_t)(BB + b) * NSEG + seg) * DD + d];
        c2[d] = s / (float)len_z[b];
    }
    __syncthreads();

    {
        const int j = tid;
        float a1 = W1b1[j], a2 = B1b1[j], a3 = W2b1[j], a4 = B2b1[j];
        #pragma unroll 8
        for (int d = 0; d < DD; ++d) {
            const float v1 = c1[d], v2 = c2[d];
            a1 += v1 * W1w1[d * HH + j];
            a2 += v1 * B1w1[d * HH + j];
            a3 += v2 * W2w1[d * HH + j];
            a4 += v2 * B2w1[d * HH + j];
        }
        hW1[j] = gelu_exact(a1);
        hB1[j] = gelu_exact(a2);
        hW2[j] = gelu_exact(a3);
        hB2[j] = gelu_exact(a4);
    }
    __syncthreads();

    if (tid < 128) {
        const int d = tid;
        float a1 = W1b2[d], a3 = W2b2[d];
        #pragma unroll 8
        for (int j = 0; j < HH; ++j) {
            a1 += hW1[j] * W1w2[j * DD + d];
            a3 += hW2[j] * W2w2[j * DD + d];
        }
        g_scale[b * DD + d] = 1.0f + 0.5f * (a1 + a3);
    } else {
        const int d = tid - 128;
        float a2 = B1b2[d], a4 = B2b2[d];
        #pragma unroll 8
        for (int j = 0; j < HH; ++j) {
            a2 += hB1[j] * B1w2[j * DD + d];
            a4 += hB2[j] * B2w2[j * DD + d];
        }
        g_bias[b * DD + d] = 0.5f * (a2 + a4);
    }
}

// ---------------- Forward ragged DFT + filter epilogue (half spectrum) -------
// Conjugate symmetry (x real, scale/bias real): only k <= l/2 stored, with
// weight w_k (2 for interior k, 1 for k=0 and k=l/2) folded into the store.
__global__ __launch_bounds__(256) void fwd_kernel(const float* __restrict__ x,
                                                  const int* __restrict__ len_x)
{
    const int b = blockIdx.y;
    const int l = len_x[b];
    const int lhalf = (l >> 1) + 1;      // rows stored: k in [0, l/2]
    const int k0 = blockIdx.x * 32;
    if (k0 >= lhalf) return;

    __shared__ ull2 tw4[LL];
    __shared__ __align__(16) float xs[32][DD];

    const int tid = threadIdx.x;
    const float invl = 1.0f / (float)l;
    for (int m = tid; m < l; m += 256) {
        float s, c;
        sincosf(TWO_PI * (float)m * invl, &s, &c);
        ull2 w; w.x = pack2(c, c); w.y = pack2(-s, -s);
        tw4[m] = w;
    }

    const int g = tid & 31;
    const int kq = tid >> 5;
    int kk[4], mm[4], ks[4];
    #pragma unroll
    for (int i = 0; i < 4; ++i) { kk[i] = k0 + kq * 4 + i; ks[i] = kk[i] % l; mm[i] = 0; }

    u64 ar[4][2] = {}, ai[4][2] = {};   // packed (d,d+1) re / im accumulators

    const float* xb_ = x + (size_t)b * LL * DD;
    float4 pf[4];

#define FWD_LOAD(T0) do {                                                   \
        _Pragma("unroll")                                                   \
        for (int j = 0; j < 4; ++j) {                                       \
            const int f4 = tid + 256 * j;                                   \
            const int r = f4 >> 5, cc = (f4 & 31) * 4;                      \
            const int t = (T0) + r;                                         \
            pf[j] = (t < l) ? *reinterpret_cast<const float4*>(             \
                                  &xb_[(size_t)t * DD + cc])                \
                            : make_float4(0.f, 0.f, 0.f, 0.f);              \
        }                                                                   \
    } while (0)

    FWD_LOAD(0);
    for (int t0 = 0; t0 < l; t0 += 32) {
        #pragma unroll
        for (int j = 0; j < 4; ++j) {
            const int f4 = tid + 256 * j;
            *reinterpret_cast<float4*>(&xs[f4 >> 5][(f4 & 31) * 4]) = pf[j];
        }
        __syncthreads();                 // first iter also covers table build
        if (t0 + 32 < l) FWD_LOAD(t0 + 32);   // LDGs in flight during compute
        #pragma unroll 4
        for (int tt = 0; tt < 32; ++tt) {
            const ull2 xa = *reinterpret_cast<const ull2*>(&xs[tt][g * 4]);
            #pragma unroll
            for (int i = 0; i < 4; ++i) {
                const ull2 w = tw4[mm[i]];
                ffma2(ar[i][0], w.x, xa.x); ffma2(ar[i][1], w.x, xa.y);
                ffma2(ai[i][0], w.y, xa.x); ffma2(ai[i][1], w.y, xa.y);
                mm[i] += ks[i]; if (mm[i] >= l) mm[i] -= l;
            }
        }
        __syncthreads();
    }
#undef FWD_LOAD

    // Epilogue: store w_k * (F*scale + bias); complex-relu is identity.
    const float4 sc = *reinterpret_cast<const float4*>(&g_scale[b * DD + g * 4]);
    const float4 bi = *reinterpret_cast<const float4*>(&g_bias[b * DD + g * 4]);
    #pragma unroll
    for (int i = 0; i < 4; ++i) {
        const int k = kk[i];
        if (k < lhalf) {
            const float w = (k == 0 || 2 * k == l) ? 1.0f : 2.0f;
            float r0, r1, r2, r3, q0, q1, q2, q3;
            unpack2(ar[i][0], r0, r1); unpack2(ar[i][1], r2, r3);
            unpack2(ai[i][0], q0, q1); unpack2(ai[i][1], q2, q3);
            const size_t base = ((size_t)b * LL + k) * DD + g * 4;
            *reinterpret_cast<float4*>(&g_Fre[base]) =
                make_float4((r0*sc.x+bi.x)*w, (r1*sc.y+bi.y)*w,
                            (r2*sc.z+bi.z)*w, (r3*sc.w+bi.w)*w);
            *reinterpret_cast<float4*>(&g_Fim[base]) =
                make_float4(q0*sc.x*w, q1*sc.y*w, q2*sc.z*w, q3*sc.w*w);
        }
    }
}

// ---------------- Inverse ragged DFT (half-spectrum sum) ----------------
// out[b,k,d] = (1/l) * sum_{j<=l/2} [cos*Fre + (-sin)*Fim] (weights pre-folded),
// for k<l; else 0.
__global__ __launch_bounds__(256) void inv_kernel(float* __restrict__ out,
                                                  const int* __restrict__ len_x)
{
    const int b = blockIdx.y;
    const int l = len_x[b];
    const int lhalf = (l >> 1) + 1;
    const int k0 = blockIdx.x * 32;
    const int tid = threadIdx.x;

    if (k0 >= l) {  // whole tile past l: zero-fill output (buffer is poisoned)
        for (int idx = tid; idx < 32 * DD; idx += 256) {
            const int k = k0 + (idx >> 7);
            out[((size_t)b * LL + k) * DD + (idx & 127)] = 0.f;
        }
        return;
    }

    __shared__ ull2 tw4[LL];
    __shared__ __align__(16) float fre[32][DD];
    __shared__ __align__(16) float fim[32][DD];

    const float invl = 1.0f / (float)l;
    for (int m = tid; m < l; m += 256) {
        float s, c;
        sincosf(TWO_PI * (float)m * invl, &s, &c);
        ull2 w; w.x = pack2(c, c); w.y = pack2(-s, -s);
        tw4[m] = w;
    }

    const int g = tid & 31;
    const int kq = tid >> 5;
    int kk[4], mm[4], ks[4];
    #pragma unroll
    for (int i = 0; i < 4; ++i) { kk[i] = k0 + kq * 4 + i; ks[i] = kk[i] % l; mm[i] = 0; }

    u64 acc[4][2] = {};   // packed (d,d+1) output accumulators

    const float* fre_g = g_Fre + (size_t)b * LL * DD;
    const float* fim_g = g_Fim + (size_t)b * LL * DD;
    float4 pr[4], pi[4];

#define INV_LOAD(T0) do {                                                   \
        _Pragma("unroll")                                                   \
        for (int j = 0; j < 4; ++j) {                                       \
            const int f4 = tid + 256 * j;                                   \
            const int r = f4 >> 5, cc = (f4 & 31) * 4;                      \
            const int t = (T0) + r;                                         \
            if (t < lhalf) {                                                \
                const size_t o = (size_t)t * DD + cc;                       \
                pr[j] = *reinterpret_cast<const float4*>(&fre_g[o]);        \
                pi[j] = *reinterpret_cast<const float4*>(&fim_g[o]);        \
            } else {                                                        \
                pr[j] = make_float4(0.f, 0.f, 0.f, 0.f);                    \
                pi[j] = make_float4(0.f, 0.f, 0.f, 0.f);                    \
            }                                                               \
        }                                                                   \
    } while (0)

    INV_LOAD(0);
    for (int t0 = 0; t0 < lhalf; t0 += 32) {
        #pragma unroll
        for (int j = 0; j < 4; ++j) {
            const int f4 = tid + 256 * j;
            *reinterpret_cast<float4*>(&fre[f4 >> 5][(f4 & 31) * 4]) = pr[j];
            *reinterpret_cast<float4*>(&fim[f4 >> 5][(f4 & 31) * 4]) = pi[j];
        }
        __syncthreads();
        if (t0 + 32 < lhalf) INV_LOAD(t0 + 32);
        #pragma unroll 4
        for (int tt = 0; tt < 32; ++tt) {
            const ull2 fa = *reinterpret_cast<const ull2*>(&fre[tt][g * 4]);
            const ull2 ga = *reinterpret_cast<const ull2*>(&fim[tt][g * 4]);
            #pragma unroll
            for (int i = 0; i < 4; ++i) {
                const ull2 w = tw4[mm[i]];
                ffma2(acc[i][0], w.x, fa.x); ffma2(acc[i][0], w.y, ga.x);
                ffma2(acc[i][1], w.x, fa.y); ffma2(acc[i][1], w.y, ga.y);
                mm[i] += ks[i]; if (mm[i] >= l) mm[i] -= l;
            }
        }
        __syncthreads();
    }
#undef INV_LOAD

    #pragma unroll
    for (int i = 0; i < 4; ++i) {
        const int k = kk[i];
        float o0 = 0.f, o1 = 0.f, o2 = 0.f, o3 = 0.f;
        if (k < l) {
            unpack2(acc[i][0], o0, o1); unpack2(acc[i][1], o2, o3);
            o0 *= invl; o1 *= invl; o2 *= invl; o3 *= invl;
        }
        *reinterpret_cast<float4*>(&out[((size_t)b * LL + k) * DD + g * 4]) =
            make_float4(o0, o1, o2, o3);
    }
}

extern "C" void kernel_launch(void* const* d_in, const int* in_sizes, int n_in,
                              void* d_out, int out_size)
{
    const float* x     = (const float*)d_in[0];
    const float* y     = (const float*)d_in[1];
    const float* z     = (const float*)d_in[2];
    const int*   len_x = (const int*)d_in[3];
    const int*   len_y = (const int*)d_in[4];
    const int*   len_z = (const int*)d_in[5];

    part_kernel<<<dim3(NSEG, 2 * BB), 128>>>(y, z);
    mlp_kernel<<<BB, 256>>>(len_y, len_z,
        (const float*)d_in[6],  (const float*)d_in[7],  (const float*)d_in[8],  (const float*)d_in[9],
        (const float*)d_in[10], (const float*)d_in[11], (const float*)d_in[12], (const float*)d_in[13],
        (const float*)d_in[14], (const float*)d_in[15], (const float*)d_in[16], (const float*)d_in[17],
        (const float*)d_in[18], (const float*)d_in[19], (const float*)d_in[20], (const float*)d_in[21]);

    fwd_kernel<<<dim3(LL / 32, BB), 256>>>(x, len_x);
    inv_kernel<<<dim3(LL / 32, BB), 256>>>((float*)d_out, len_x);
}